// round 4
// baseline (speedup 1.0000x reference)
#include <cuda_runtime.h>
#include <math_constants.h>

#define NN  100000
#define EE  1600000
#define DIMK 128

// ---------------- device scratch (allocation-free rule) ----------------
__device__ float g_q[NN * DIMK];
__device__ float g_k[NN * DIMK];
__device__ float g_v[NN * DIMK];
__device__ float g_agg[NN * DIMK];
__device__ int   g_cnt[NN];
__device__ int   g_off[NN + 1];
__device__ int   g_cur[NN];
__device__ int   g_csrc[EE];

// ---------------- fused QKV GEMM ----------------
// C_w[M,128] = A[M,128] @ W_w[128,128] + b_w  for w in {q,k,v}
// BM=64, BN=64 (grid.y=2), BK=64 (2 K-steps). Per K-step the A tile is loaded
// once and reused for all three weight matrices (B streamed through one buffer).
// Static smem: 64*68*4 + 64*64*4 = 33,792 B  (< 48 KB limit).
#define QBK 64

__global__ __launch_bounds__(256) void qkv_gemm_kernel(
        const float* __restrict__ A,
        const float* __restrict__ Wq, const float* __restrict__ bq,
        const float* __restrict__ Wk, const float* __restrict__ bk,
        const float* __restrict__ Wv, const float* __restrict__ bv,
        int M) {
    __shared__ __align__(16) float As[64][QBK + 4];
    __shared__ __align__(16) float Bs[QBK][64];

    const int t  = threadIdx.x;
    const int tx = t & 15;          // n-direction
    const int ty = t >> 4;          // m-direction
    const int row0 = blockIdx.x * 64;
    const int col0 = blockIdx.y * 64;

    const float* Ws[3]; const float* bs[3];
    float* Cs[3];
    Ws[0] = Wq; Ws[1] = Wk; Ws[2] = Wv;
    bs[0] = bq; bs[1] = bk; bs[2] = bv;
    Cs[0] = g_q; Cs[1] = g_k; Cs[2] = g_v;

    float acc[3][4][4];
#pragma unroll
    for (int w = 0; w < 3; w++)
#pragma unroll
        for (int i = 0; i < 4; i++)
#pragma unroll
            for (int j = 0; j < 4; j++) acc[w][i][j] = 0.f;

    for (int k0 = 0; k0 < DIMK; k0 += QBK) {
        __syncthreads();   // protect As/Bs from previous iteration's readers
        // Load A tile (64 rows x 64 cols): 1024 float4, 4 per thread.
#pragma unroll
        for (int i = 0; i < 4; i++) {
            int idx = t + i * 256;
            int r  = idx >> 4;           // 0..63
            int c4 = (idx & 15) * 4;     // 0..60
            int gr = row0 + r;
            float4 av = make_float4(0.f, 0.f, 0.f, 0.f);
            if (gr < M) av = *(const float4*)(A + (long long)gr * DIMK + k0 + c4);
            *(float4*)&As[r][c4] = av;
        }

        for (int w = 0; w < 3; w++) {
            __syncthreads();   // As ready (w=0) / prior Bs consumers done (w>0)
            // Load B tile (64 rows x 64 cols): 1024 float4, 4 per thread.
            const float* W = Ws[w];
#pragma unroll
            for (int i = 0; i < 4; i++) {
                int idx = t + i * 256;
                int r  = idx >> 4;
                int c4 = (idx & 15) * 4;
                *(float4*)&Bs[r][c4] = *(const float4*)(W + (k0 + r) * DIMK + col0 + c4);
            }
            __syncthreads();

#pragma unroll 8
            for (int k = 0; k < QBK; k++) {
                float4 b = *(float4*)&Bs[k][tx * 4];
                float a0 = As[ty * 4 + 0][k];
                float a1 = As[ty * 4 + 1][k];
                float a2 = As[ty * 4 + 2][k];
                float a3 = As[ty * 4 + 3][k];
                acc[w][0][0] += a0 * b.x; acc[w][0][1] += a0 * b.y; acc[w][0][2] += a0 * b.z; acc[w][0][3] += a0 * b.w;
                acc[w][1][0] += a1 * b.x; acc[w][1][1] += a1 * b.y; acc[w][1][2] += a1 * b.z; acc[w][1][3] += a1 * b.w;
                acc[w][2][0] += a2 * b.x; acc[w][2][1] += a2 * b.y; acc[w][2][2] += a2 * b.z; acc[w][2][3] += a2 * b.w;
                acc[w][3][0] += a3 * b.x; acc[w][3][1] += a3 * b.y; acc[w][3][2] += a3 * b.z; acc[w][3][3] += a3 * b.w;
            }
        }
    }

#pragma unroll
    for (int w = 0; w < 3; w++) {
        float4 bb = *(const float4*)(bs[w] + col0 + tx * 4);
        float* C = Cs[w];
#pragma unroll
        for (int i = 0; i < 4; i++) {
            int gr = row0 + ty * 4 + i;
            if (gr < M) {
                float4 o;
                o.x = acc[w][i][0] + bb.x;
                o.y = acc[w][i][1] + bb.y;
                o.z = acc[w][i][2] + bb.z;
                o.w = acc[w][i][3] + bb.w;
                *(float4*)(C + (long long)gr * DIMK + col0 + tx * 4) = o;
            }
        }
    }
}

// ---------------- single GEMM (for O projection) ----------------
#define BM 64
#define BN 64
#define BK 32

__global__ __launch_bounds__(256) void gemm_kernel(
        const float* __restrict__ B,
        const float* __restrict__ bias,
        float* __restrict__ C, int M) {
    const float* A = g_agg;
    __shared__ __align__(16) float As[BM][BK + 4];
    __shared__ __align__(16) float Bs[BK][BN];

    const int t  = threadIdx.x;
    const int tx = t & 15;
    const int ty = t >> 4;
    const int row0 = blockIdx.x * BM;
    const int col0 = blockIdx.y * BN;

    float acc[4][4];
#pragma unroll
    for (int i = 0; i < 4; i++)
#pragma unroll
        for (int j = 0; j < 4; j++) acc[i][j] = 0.f;

    const int arow = t >> 3;
    const int acol = (t & 7) * 4;
    const int brow = t >> 4;
    const int bcol = (t & 15) * 4;

    for (int k0 = 0; k0 < DIMK; k0 += BK) {
#pragma unroll
        for (int rr = 0; rr < 2; rr++) {
            int r  = arow + rr * 32;
            int gr = row0 + r;
            float4 av = make_float4(0.f, 0.f, 0.f, 0.f);
            if (gr < M) av = *(const float4*)(A + (long long)gr * DIMK + k0 + acol);
            *(float4*)&As[r][acol] = av;
        }
#pragma unroll
        for (int rr = 0; rr < 2; rr++) {
            int r = brow + rr * 16;
            float4 bv = *(const float4*)(B + (k0 + r) * DIMK + col0 + bcol);
            *(float4*)&Bs[r][bcol] = bv;
        }
        __syncthreads();

#pragma unroll
        for (int k = 0; k < BK; k++) {
            float4 b = *(float4*)&Bs[k][tx * 4];
            float a0 = As[ty * 4 + 0][k];
            float a1 = As[ty * 4 + 1][k];
            float a2 = As[ty * 4 + 2][k];
            float a3 = As[ty * 4 + 3][k];
            acc[0][0] += a0 * b.x; acc[0][1] += a0 * b.y; acc[0][2] += a0 * b.z; acc[0][3] += a0 * b.w;
            acc[1][0] += a1 * b.x; acc[1][1] += a1 * b.y; acc[1][2] += a1 * b.z; acc[1][3] += a1 * b.w;
            acc[2][0] += a2 * b.x; acc[2][1] += a2 * b.y; acc[2][2] += a2 * b.z; acc[2][3] += a2 * b.w;
            acc[3][0] += a3 * b.x; acc[3][1] += a3 * b.y; acc[3][2] += a3 * b.z; acc[3][3] += a3 * b.w;
        }
        __syncthreads();
    }

    float4 bb = *(const float4*)(bias + col0 + tx * 4);
#pragma unroll
    for (int i = 0; i < 4; i++) {
        int gr = row0 + ty * 4 + i;
        if (gr < M) {
            float4 o;
            o.x = acc[i][0] + bb.x;
            o.y = acc[i][1] + bb.y;
            o.z = acc[i][2] + bb.z;
            o.w = acc[i][3] + bb.w;
            *(float4*)(C + (long long)gr * DIMK + col0 + tx * 4) = o;
        }
    }
}

// ---------------- CSR build ----------------
__global__ void zero_cnt_kernel() {
    int i = blockIdx.x * blockDim.x + threadIdx.x;
    if (i < NN) g_cnt[i] = 0;
}

__global__ void hist_kernel(const int* __restrict__ dst) {
    int e = blockIdx.x * blockDim.x + threadIdx.x;
    if (e < EE) atomicAdd(&g_cnt[dst[e]], 1);
}

// single-block exclusive scan over NN counts
__global__ void scan_kernel() {
    __shared__ int sums[1024];
    const int t = threadIdx.x;
    const int CHUNK = (NN + 1023) / 1024;
    const int begin = t * CHUNK;
    const int end   = min(begin + CHUNK, NN);
    int s = 0;
    for (int i = begin; i < end; i++) s += g_cnt[i];
    sums[t] = s;
    __syncthreads();
    for (int off = 1; off < 1024; off <<= 1) {
        int val = (t >= off) ? sums[t - off] : 0;
        __syncthreads();
        sums[t] += val;
        __syncthreads();
    }
    int run = (t == 0) ? 0 : sums[t - 1];
    for (int i = begin; i < end; i++) {
        g_off[i] = run;
        g_cur[i] = run;
        run += g_cnt[i];
    }
    if (t == 0) g_off[NN] = sums[1023];
}

__global__ void scatter_kernel(const int* __restrict__ src,
                               const int* __restrict__ dst) {
    int e = blockIdx.x * blockDim.x + threadIdx.x;
    if (e < EE) {
        int p = atomicAdd(&g_cur[dst[e]], 1);
        g_csrc[p] = src[e];
    }
}

// ---------------- attention: one warp per dst node, online softmax ----------------
// lane l owns dims [4l, 4l+4); head = l/4 (HD=16 -> 4 lanes per head)
__global__ void attn_kernel() {
    const int warp = (blockIdx.x * blockDim.x + threadIdx.x) >> 5;
    if (warp >= NN) return;
    const int lane = threadIdx.x & 31;

    const float4 kv = *(const float4*)(g_k + (long long)warp * DIMK + lane * 4);

    float m = -CUDART_INF_F;
    float z = 0.f;
    float4 acc = make_float4(0.f, 0.f, 0.f, 0.f);

    const int beg = g_off[warp];
    const int end = g_off[warp + 1];

    for (int i = beg; i < end; i++) {
        int s = g_csrc[i];
        const float4 qv = *(const float4*)(g_q + (long long)s * DIMK + lane * 4);
        float p = qv.x * kv.x + qv.y * kv.y + qv.z * kv.z + qv.w * kv.w;
        p += __shfl_xor_sync(0xFFFFFFFFu, p, 1);
        p += __shfl_xor_sync(0xFFFFFFFFu, p, 2);
        p *= 0.25f;  // 1/sqrt(HD=16)

        float mn   = fmaxf(m, p);
        float corr = __expf(m - mn);   // first iter: exp(-inf) = 0
        float w    = __expf(p - mn);
        z = z * corr + w;

        const float4 vv = *(const float4*)(g_v + (long long)s * DIMK + lane * 4);
        acc.x = acc.x * corr + w * vv.x;
        acc.y = acc.y * corr + w * vv.y;
        acc.z = acc.z * corr + w * vv.z;
        acc.w = acc.w * corr + w * vv.w;
        m = mn;
    }

    float inv = (z > 0.f) ? (1.f / z) : 0.f;
    acc.x *= inv; acc.y *= inv; acc.z *= inv; acc.w *= inv;
    *(float4*)(g_agg + (long long)warp * DIMK + lane * 4) = acc;
}

// ---------------- launch ----------------
extern "C" void kernel_launch(void* const* d_in, const int* in_sizes, int n_in,
                              void* d_out, int out_size) {
    const float* x   = (const float*)d_in[0];
    const int*   src = (const int*)d_in[1];
    const int*   dst = (const int*)d_in[2];
    const float* Wq  = (const float*)d_in[3];
    const float* bq  = (const float*)d_in[4];
    const float* Wk  = (const float*)d_in[5];
    const float* bk  = (const float*)d_in[6];
    const float* Wv  = (const float*)d_in[7];
    const float* bv  = (const float*)d_in[8];
    const float* Wo  = (const float*)d_in[9];
    const float* bo  = (const float*)d_in[10];
    float* out = (float*)d_out;

    dim3 qkv_grid((NN + 63) / 64, 2);
    qkv_gemm_kernel<<<qkv_grid, 256>>>(x, Wq, bq, Wk, bk, Wv, bv, NN);

    zero_cnt_kernel<<<(NN + 255) / 256, 256>>>();
    hist_kernel<<<(EE + 255) / 256, 256>>>(dst);
    scan_kernel<<<1, 1024>>>();
    scatter_kernel<<<(EE + 255) / 256, 256>>>(src, dst);

    attn_kernel<<<(NN * 32 + 255) / 256, 256>>>();

    dim3 gemm_grid((NN + BM - 1) / BM, DIMK / BN);
    gemm_kernel<<<gemm_grid, 256>>>(Wo, bo, out, NN);
}

// round 5
// speedup vs baseline: 1.2653x; 1.2653x over previous
#include <cuda_runtime.h>
#include <math_constants.h>

#define NN  100000
#define EE  1600000
#define DIMK 128

#define SCAN_T 256
#define NBLK ((NN + SCAN_T - 1) / SCAN_T)   // 391

// ---------------- device scratch (allocation-free rule) ----------------
__device__ float g_q[NN * DIMK];
__device__ float g_k[NN * DIMK];
__device__ float g_v[NN * DIMK];
__device__ float g_agg[NN * DIMK];
__device__ int   g_cnt[NN];
__device__ int   g_off[NN + 1];
__device__ int   g_cur[NN];
__device__ int   g_csrc[EE];
__device__ int   g_bsum[NBLK];
__device__ int   g_bpre[NBLK];

// ---------------- fused QKV GEMM ----------------
// C_w[M,128] = A[M,128] @ W_w[128,128] + b_w  for w in {q,k,v}
// BM=64, BN=64 (grid.y=2), BK=64 (2 K-steps). Per K-step the A tile is loaded
// once and reused for all three weight matrices (B streamed through one buffer).
#define QBK 64

__global__ __launch_bounds__(256) void qkv_gemm_kernel(
        const float* __restrict__ A,
        const float* __restrict__ Wq, const float* __restrict__ bq,
        const float* __restrict__ Wk, const float* __restrict__ bk,
        const float* __restrict__ Wv, const float* __restrict__ bv,
        int M) {
    __shared__ __align__(16) float As[64][QBK + 4];
    __shared__ __align__(16) float Bs[QBK][64];

    const int t  = threadIdx.x;
    const int tx = t & 15;          // n-direction
    const int ty = t >> 4;          // m-direction
    const int row0 = blockIdx.x * 64;
    const int col0 = blockIdx.y * 64;

    const float* Ws[3]; const float* bs[3];
    float* Cs[3];
    Ws[0] = Wq; Ws[1] = Wk; Ws[2] = Wv;
    bs[0] = bq; bs[1] = bk; bs[2] = bv;
    Cs[0] = g_q; Cs[1] = g_k; Cs[2] = g_v;

    float acc[3][4][4];
#pragma unroll
    for (int w = 0; w < 3; w++)
#pragma unroll
        for (int i = 0; i < 4; i++)
#pragma unroll
            for (int j = 0; j < 4; j++) acc[w][i][j] = 0.f;

    for (int k0 = 0; k0 < DIMK; k0 += QBK) {
        __syncthreads();
#pragma unroll
        for (int i = 0; i < 4; i++) {
            int idx = t + i * 256;
            int r  = idx >> 4;           // 0..63
            int c4 = (idx & 15) * 4;     // 0..60
            int gr = row0 + r;
            float4 av = make_float4(0.f, 0.f, 0.f, 0.f);
            if (gr < M) av = *(const float4*)(A + (long long)gr * DIMK + k0 + c4);
            *(float4*)&As[r][c4] = av;
        }

        for (int w = 0; w < 3; w++) {
            __syncthreads();
            const float* W = Ws[w];
#pragma unroll
            for (int i = 0; i < 4; i++) {
                int idx = t + i * 256;
                int r  = idx >> 4;
                int c4 = (idx & 15) * 4;
                *(float4*)&Bs[r][c4] = *(const float4*)(W + (k0 + r) * DIMK + col0 + c4);
            }
            __syncthreads();

#pragma unroll 8
            for (int k = 0; k < QBK; k++) {
                float4 b = *(float4*)&Bs[k][tx * 4];
                float a0 = As[ty * 4 + 0][k];
                float a1 = As[ty * 4 + 1][k];
                float a2 = As[ty * 4 + 2][k];
                float a3 = As[ty * 4 + 3][k];
                acc[w][0][0] += a0 * b.x; acc[w][0][1] += a0 * b.y; acc[w][0][2] += a0 * b.z; acc[w][0][3] += a0 * b.w;
                acc[w][1][0] += a1 * b.x; acc[w][1][1] += a1 * b.y; acc[w][1][2] += a1 * b.z; acc[w][1][3] += a1 * b.w;
                acc[w][2][0] += a2 * b.x; acc[w][2][1] += a2 * b.y; acc[w][2][2] += a2 * b.z; acc[w][2][3] += a2 * b.w;
                acc[w][3][0] += a3 * b.x; acc[w][3][1] += a3 * b.y; acc[w][3][2] += a3 * b.z; acc[w][3][3] += a3 * b.w;
            }
        }
    }

#pragma unroll
    for (int w = 0; w < 3; w++) {
        float4 bb = *(const float4*)(bs[w] + col0 + tx * 4);
        float* C = Cs[w];
#pragma unroll
        for (int i = 0; i < 4; i++) {
            int gr = row0 + ty * 4 + i;
            if (gr < M) {
                float4 o;
                o.x = acc[w][i][0] + bb.x;
                o.y = acc[w][i][1] + bb.y;
                o.z = acc[w][i][2] + bb.z;
                o.w = acc[w][i][3] + bb.w;
                *(float4*)(C + (long long)gr * DIMK + col0 + tx * 4) = o;
            }
        }
    }
}

// ---------------- single GEMM (for O projection) ----------------
#define BM 64
#define BN 64
#define BK 32

__global__ __launch_bounds__(256) void gemm_kernel(
        const float* __restrict__ B,
        const float* __restrict__ bias,
        float* __restrict__ C, int M) {
    const float* A = g_agg;
    __shared__ __align__(16) float As[BM][BK + 4];
    __shared__ __align__(16) float Bs[BK][BN];

    const int t  = threadIdx.x;
    const int tx = t & 15;
    const int ty = t >> 4;
    const int row0 = blockIdx.x * BM;
    const int col0 = blockIdx.y * BN;

    float acc[4][4];
#pragma unroll
    for (int i = 0; i < 4; i++)
#pragma unroll
        for (int j = 0; j < 4; j++) acc[i][j] = 0.f;

    const int arow = t >> 3;
    const int acol = (t & 7) * 4;
    const int brow = t >> 4;
    const int bcol = (t & 15) * 4;

    for (int k0 = 0; k0 < DIMK; k0 += BK) {
#pragma unroll
        for (int rr = 0; rr < 2; rr++) {
            int r  = arow + rr * 32;
            int gr = row0 + r;
            float4 av = make_float4(0.f, 0.f, 0.f, 0.f);
            if (gr < M) av = *(const float4*)(A + (long long)gr * DIMK + k0 + acol);
            *(float4*)&As[r][acol] = av;
        }
#pragma unroll
        for (int rr = 0; rr < 2; rr++) {
            int r = brow + rr * 16;
            float4 bv = *(const float4*)(B + (k0 + r) * DIMK + col0 + bcol);
            *(float4*)&Bs[r][bcol] = bv;
        }
        __syncthreads();

#pragma unroll
        for (int k = 0; k < BK; k++) {
            float4 b = *(float4*)&Bs[k][tx * 4];
            float a0 = As[ty * 4 + 0][k];
            float a1 = As[ty * 4 + 1][k];
            float a2 = As[ty * 4 + 2][k];
            float a3 = As[ty * 4 + 3][k];
            acc[0][0] += a0 * b.x; acc[0][1] += a0 * b.y; acc[0][2] += a0 * b.z; acc[0][3] += a0 * b.w;
            acc[1][0] += a1 * b.x; acc[1][1] += a1 * b.y; acc[1][2] += a1 * b.z; acc[1][3] += a1 * b.w;
            acc[2][0] += a2 * b.x; acc[2][1] += a2 * b.y; acc[2][2] += a2 * b.z; acc[2][3] += a2 * b.w;
            acc[3][0] += a3 * b.x; acc[3][1] += a3 * b.y; acc[3][2] += a3 * b.z; acc[3][3] += a3 * b.w;
        }
        __syncthreads();
    }

    float4 bb = *(const float4*)(bias + col0 + tx * 4);
#pragma unroll
    for (int i = 0; i < 4; i++) {
        int gr = row0 + ty * 4 + i;
        if (gr < M) {
            float4 o;
            o.x = acc[i][0] + bb.x;
            o.y = acc[i][1] + bb.y;
            o.z = acc[i][2] + bb.z;
            o.w = acc[i][3] + bb.w;
            *(float4*)(C + (long long)gr * DIMK + col0 + tx * 4) = o;
        }
    }
}

// ---------------- CSR build ----------------
__global__ void zero_cnt_kernel() {
    int i = blockIdx.x * blockDim.x + threadIdx.x;
    if (i < NN) g_cnt[i] = 0;
}

__global__ void hist_kernel(const int* __restrict__ dst) {
    int e = blockIdx.x * blockDim.x + threadIdx.x;
    if (e < EE) atomicAdd(&g_cnt[dst[e]], 1);
}

// Phase A: per-block reduce of 256 counts
__global__ void scan_phaseA_kernel() {
    __shared__ int sm[SCAN_T];
    int i = blockIdx.x * SCAN_T + threadIdx.x;
    sm[threadIdx.x] = (i < NN) ? g_cnt[i] : 0;
    __syncthreads();
#pragma unroll
    for (int s = SCAN_T / 2; s > 0; s >>= 1) {
        if (threadIdx.x < s) sm[threadIdx.x] += sm[threadIdx.x + s];
        __syncthreads();
    }
    if (threadIdx.x == 0) g_bsum[blockIdx.x] = sm[0];
}

// Phase B: 1 block scans the 391 block sums (exclusive)
__global__ void scan_phaseB_kernel() {
    __shared__ int sm[512];
    int t = threadIdx.x;
    int v = (t < NBLK) ? g_bsum[t] : 0;
    sm[t] = v;
    __syncthreads();
#pragma unroll
    for (int off = 1; off < 512; off <<= 1) {
        int x = (t >= off) ? sm[t - off] : 0;
        __syncthreads();
        sm[t] += x;
        __syncthreads();
    }
    if (t < NBLK) g_bpre[t] = sm[t] - v;   // exclusive prefix
}

// Phase C: block-local exclusive scan + block prefix -> g_off, g_cur
__global__ void scan_phaseC_kernel() {
    __shared__ int sm[SCAN_T];
    int i = blockIdx.x * SCAN_T + threadIdx.x;
    int v = (i < NN) ? g_cnt[i] : 0;
    sm[threadIdx.x] = v;
    __syncthreads();
#pragma unroll
    for (int off = 1; off < SCAN_T; off <<= 1) {
        int x = (threadIdx.x >= off) ? sm[threadIdx.x - off] : 0;
        __syncthreads();
        sm[threadIdx.x] += x;
        __syncthreads();
    }
    if (i < NN) {
        int excl = sm[threadIdx.x] - v + g_bpre[blockIdx.x];
        g_off[i] = excl;
        g_cur[i] = excl;
    }
    if (i == NN - 1) g_off[NN] = EE;   // total edge count is exact by construction
}

__global__ void scatter_kernel(const int* __restrict__ src,
                               const int* __restrict__ dst) {
    int e = blockIdx.x * blockDim.x + threadIdx.x;
    if (e < EE) {
        int p = atomicAdd(&g_cur[dst[e]], 1);
        g_csrc[p] = src[e];
    }
}

// ---------------- attention: one warp per dst node, online softmax ----------------
// lane l owns dims [4l, 4l+4); head = l/4 (HD=16 -> 4 lanes per head)
__global__ void attn_kernel() {
    const int warp = (blockIdx.x * blockDim.x + threadIdx.x) >> 5;
    if (warp >= NN) return;
    const int lane = threadIdx.x & 31;

    const float4 kv = *(const float4*)(g_k + (long long)warp * DIMK + lane * 4);

    float m = -CUDART_INF_F;
    float z = 0.f;
    float4 acc = make_float4(0.f, 0.f, 0.f, 0.f);

    const int beg = g_off[warp];
    const int end = g_off[warp + 1];

    for (int i = beg; i < end; i++) {
        int s = g_csrc[i];
        const float4 qv = *(const float4*)(g_q + (long long)s * DIMK + lane * 4);
        float p = qv.x * kv.x + qv.y * kv.y + qv.z * kv.z + qv.w * kv.w;
        p += __shfl_xor_sync(0xFFFFFFFFu, p, 1);
        p += __shfl_xor_sync(0xFFFFFFFFu, p, 2);
        p *= 0.25f;  // 1/sqrt(HD=16)

        float mn   = fmaxf(m, p);
        float corr = __expf(m - mn);   // first iter: exp(-inf) = 0
        float w    = __expf(p - mn);
        z = z * corr + w;

        const float4 vv = *(const float4*)(g_v + (long long)s * DIMK + lane * 4);
        acc.x = acc.x * corr + w * vv.x;
        acc.y = acc.y * corr + w * vv.y;
        acc.z = acc.z * corr + w * vv.z;
        acc.w = acc.w * corr + w * vv.w;
        m = mn;
    }

    float inv = (z > 0.f) ? (1.f / z) : 0.f;
    acc.x *= inv; acc.y *= inv; acc.z *= inv; acc.w *= inv;
    *(float4*)(g_agg + (long long)warp * DIMK + lane * 4) = acc;
}

// ---------------- launch ----------------
extern "C" void kernel_launch(void* const* d_in, const int* in_sizes, int n_in,
                              void* d_out, int out_size) {
    const float* x   = (const float*)d_in[0];
    const int*   src = (const int*)d_in[1];
    const int*   dst = (const int*)d_in[2];
    const float* Wq  = (const float*)d_in[3];
    const float* bq  = (const float*)d_in[4];
    const float* Wk  = (const float*)d_in[5];
    const float* bk  = (const float*)d_in[6];
    const float* Wv  = (const float*)d_in[7];
    const float* bv  = (const float*)d_in[8];
    const float* Wo  = (const float*)d_in[9];
    const float* bo  = (const float*)d_in[10];
    float* out = (float*)d_out;

    dim3 qkv_grid((NN + 63) / 64, 2);
    qkv_gemm_kernel<<<qkv_grid, 256>>>(x, Wq, bq, Wk, bk, Wv, bv, NN);

    zero_cnt_kernel<<<(NN + 255) / 256, 256>>>();
    hist_kernel<<<(EE + 255) / 256, 256>>>(dst);
    scan_phaseA_kernel<<<NBLK, SCAN_T>>>();
    scan_phaseB_kernel<<<1, 512>>>();
    scan_phaseC_kernel<<<NBLK, SCAN_T>>>();
    scatter_kernel<<<(EE + 255) / 256, 256>>>(src, dst);

    attn_kernel<<<(NN * 32 + 255) / 256, 256>>>();

    dim3 gemm_grid((NN + BM - 1) / BM, DIMK / BN);
    gemm_kernel<<<gemm_grid, 256>>>(Wo, bo, out, NN);
}